// round 15
// baseline (speedup 1.0000x reference)
#include <cuda_runtime.h>
#include <cuda_fp16.h>
#include <cuda_bf16.h>
#include <cstdint>

// Problem constants (fixed by the dataset)
#define BB   16
#define SS   2048
#define DD   240
#define EE   8
#define TT   (BB * SS)        // 32768 tokens

#define KCH     16            // k per chunk (one mma K)
#define NCHUNK  (DD / KCH)    // 15
#define BM      128           // tokens per CTA tile
#define BN      80            // output cols per CTA (grid.y = 3)
#define STRB    48            // smem row stride in BYTES (conflict-free ldmatrix)
#define NSTAGE  4             // cp.async pipeline stages
#define GTOK    256           // tokens per gate block

// ---------------------------------------------------------------------------
// Device-global scratch (no runtime allocation allowed)
// ---------------------------------------------------------------------------
__device__ int   g_cnt[EE];
__device__ int   g_tok[EE][TT];       // packed: (token << 1) | slot
__device__ float g_gw [EE][TT];
__device__ __align__(16) unsigned short g_xf[(size_t)TT * DD];       // fp16 x
__device__ __align__(16) unsigned short g_wf[(size_t)EE * DD * DD];  // fp16 W
__device__ __align__(16) float g_part[2][(size_t)TT * DD];           // per-slot partials

// ---------------------------------------------------------------------------
// PTX helpers
// ---------------------------------------------------------------------------
__device__ __forceinline__ void cp16(uint32_t dst, const void* src, int sz) {
    asm volatile("cp.async.ca.shared.global [%0], [%1], 16, %2;"
                 :: "r"(dst), "l"(src), "r"(sz));
}
#define CP_COMMIT() asm volatile("cp.async.commit_group;")
#define CP_WAIT(n)  asm volatile("cp.async.wait_group %0;" :: "n"(n))

__device__ __forceinline__ void ldm_x4(uint32_t (&r)[4], uint32_t addr) {
    asm volatile("ldmatrix.sync.aligned.m8n8.x4.shared.b16 {%0,%1,%2,%3}, [%4];"
                 : "=r"(r[0]), "=r"(r[1]), "=r"(r[2]), "=r"(r[3]) : "r"(addr));
}
__device__ __forceinline__ void mma_fp16(float (&d)[4], const uint32_t (&a)[4],
                                         uint32_t b0, uint32_t b1) {
    asm volatile("mma.sync.aligned.m16n8k16.row.col.f32.f16.f16.f32 "
                 "{%0,%1,%2,%3}, {%4,%5,%6,%7}, {%8,%9}, {%0,%1,%2,%3};"
                 : "+f"(d[0]), "+f"(d[1]), "+f"(d[2]), "+f"(d[3])
                 : "r"(a[0]), "r"(a[1]), "r"(a[2]), "r"(a[3]), "r"(b0), "r"(b1));
}
__device__ __forceinline__ uint32_t smem_u32(const void* p) {
    uint32_t a;
    asm("{ .reg .u64 t; cvta.to.shared.u64 t, %1; cvt.u32.u64 %0, t; }" : "=r"(a) : "l"(p));
    return a;
}

// ---------------------------------------------------------------------------
// Kernel 1: W fp32 -> fp16, 8 elems/thread. Also zeroes expert counters.
// ---------------------------------------------------------------------------
__global__ __launch_bounds__(256)
void conv_kernel(const float* __restrict__ src,
                 unsigned short* __restrict__ df, int n8) {
    if (blockIdx.x == 0 && threadIdx.x < EE) g_cnt[threadIdx.x] = 0;
    int i = blockIdx.x * blockDim.x + threadIdx.x;
    if (i >= n8) return;
    const float4* s4 = (const float4*)(src + (size_t)i * 8);
    float4 v0 = s4[0], v1 = s4[1];
    float v[8] = {v0.x, v0.y, v0.z, v0.w, v1.x, v1.y, v1.z, v1.w};
    unsigned short h[8];
#pragma unroll
    for (int j = 0; j < 8; j++) {
        __half hv = __float2half_rn(v[j]);
        h[j] = *(unsigned short*)&hv;
    }
    *(uint4*)(df + (size_t)i * 8) = *(uint4*)h;
}

// ---------------------------------------------------------------------------
// Kernel 2: fused gating + scatter. Block = 256 threads = 256 tokens.
// gate_w staged in smem; x staged in 256x16 chunks (stride 17 -> conflict-
// free column reads), fp16 conversion of x folded into the load. One thread
// per token: 8 logit accs, scalar top-2 + 2-way softmax, then warp-
// aggregated atomic scatter into per-expert lists. NO shuffles.
// ---------------------------------------------------------------------------
__global__ __launch_bounds__(256)
void gate_kernel(const float* __restrict__ x,
                 const float* __restrict__ gw,
                 const float* __restrict__ gb) {
    __shared__ float gws[EE * DD];        // 7680 B
    __shared__ float xs[GTOK][17];        // 17408 B, stride 17 (conflict-free)

    const int tid  = threadIdx.x;
    const int t0   = blockIdx.x * GTOK;
    const int lane = tid & 31;

    for (int i = tid; i < EE * DD; i += 256) gws[i] = gw[i];

    float acc[EE] = {};
    for (int c = 0; c < NCHUNK; c++) {
        __syncthreads();                  // prev chunk consumed (and gws ready)
#pragma unroll
        for (int i = 0; i < 16; i++) {
            int idx = tid + 256 * i;      // 0..4095
            int r = idx >> 4, k = idx & 15;
            float v = x[(size_t)(t0 + r) * DD + c * 16 + k];
            xs[r][k] = v;
            __half hv = __float2half_rn(v);
            g_xf[(size_t)(t0 + r) * DD + c * 16 + k] = *(unsigned short*)&hv;
        }
        __syncthreads();
#pragma unroll
        for (int k = 0; k < 16; k++) {
            float xv = xs[tid][k];
#pragma unroll
            for (int e = 0; e < EE; e++)
                acc[e] += xv * gws[e * DD + c * 16 + k];
        }
    }

#pragma unroll
    for (int e = 0; e < EE; e++) acc[e] += gb[e];

    // top-2 (earliest index on ties, matching jax top_k)
    int b1 = 0;
#pragma unroll
    for (int e = 1; e < EE; e++) if (acc[e] > acc[b1]) b1 = e;
    int b2 = (b1 == 0) ? 1 : 0;
#pragma unroll
    for (int e = 0; e < EE; e++) {
        if (e == b1 || e == b2) continue;
        if (acc[e] > acc[b2]) b2 = e;
    }
    float m  = fmaxf(acc[b1], acc[b2]);
    float e1 = __expf(acc[b1] - m);
    float e2 = __expf(acc[b2] - m);
    float inv = 1.f / (e1 + e2);
    float w1 = e1 * inv, w2 = e2 * inv;

    // fused scatter: warp-aggregated atomics, packed (token<<1)|slot
    const int t = t0 + tid;
#pragma unroll
    for (int slot = 0; slot < 2; slot++) {
        int   e = slot ? b2 : b1;
        float w = slot ? w2 : w1;
        unsigned mask = __match_any_sync(0xffffffffu, e);
        int leader = __ffs(mask) - 1;
        int rank   = __popc(mask & ((1u << lane) - 1));
        int base = 0;
        if (lane == leader) base = atomicAdd(&g_cnt[e], __popc(mask));
        base = __shfl_sync(mask, base, leader);
        int pos = base + rank;
        g_tok[e][pos] = (t << 1) | slot;
        g_gw [e][pos] = w;
    }
}

// ---------------------------------------------------------------------------
// Kernel 3: grouped expert GEMM on warp tensor cores, fp16 single-term.
// grid = (TT/BM, 3, E). 128 threads = 4 m-warps x 1 n-warp (warp tile 32x80).
// B fragments loaded as jt-pairs via ldm_x4. 4-stage cp.async pipeline,
// one __syncthreads per chunk. Epilogue: plain stores into g_part.
// ---------------------------------------------------------------------------
#define HDR     1024
#define A_SZ    (BM * STRB)            // 6144 B per A stage
#define B_SZ    (BN * STRB)            // 3840 B per B stage
#define STG_SZ  (A_SZ + B_SZ)          // 9984 B per stage
#define OFF_A   0
#define OFF_B   A_SZ
#define SMEM_TOT (HDR + NSTAGE * STG_SZ)   // 40960 B -> 4 CTAs/SM

__global__ __launch_bounds__(128, 4)
void moe_mma_kernel(const float* __restrict__ eb) {
    const int e   = blockIdx.z;
    const int cnt = g_cnt[e];
    const int m0  = blockIdx.x * BM;
    if (m0 >= cnt) return;
    const int nb  = blockIdx.y * BN;      // 0, 80, 160

    extern __shared__ __align__(16) char smem[];
    int*   tsp = (int*)  smem;
    float* wsp = (float*)(smem + 512);
    const uint32_t sb = smem_u32(smem);

    const int tid  = threadIdx.x;
    const int lane = tid & 31;
    const int wid  = tid >> 5;           // m-warp 0..3
    const int m0w  = wid * 32;

    if (tid < BM) {
        int gr = m0 + tid;
        if (gr < cnt) { tsp[tid] = g_tok[e][gr]; wsp[tid] = g_gw[e][gr]; }
        else          { tsp[tid] = -1;           wsp[tid] = 0.f; }
    }
    __syncthreads();

    // --- cp.async issue for chunk c into stage stg ---
    auto issue = [&](int c, int stg) {
        uint32_t base = sb + HDR + stg * STG_SZ;
#pragma unroll
        for (int s = tid; s < BM * 2; s += 128) {
            int row = s >> 1, h = s & 1;
            int v = tsp[row];
            size_t so = (size_t)((v < 0) ? 0 : (v >> 1)) * DD + c * KCH + h * 8;
            int  sz = (v >= 0) ? 16 : 0;
            uint32_t d = (uint32_t)(row * STRB + h * 16);
            cp16(base + OFF_A + d, g_xf + so, sz);
        }
#pragma unroll
        for (int s = tid; s < BN * 2; s += 128) {
            int row = s >> 1, h = s & 1;
            size_t so = ((size_t)e * DD + nb + row) * DD + c * KCH + h * 8;
            uint32_t d = (uint32_t)(row * STRB + h * 16);
            cp16(base + OFF_B + d, g_wf + so, 16);
        }
        CP_COMMIT();
    };

    const uint32_t a_off0 = (uint32_t)((m0w + (lane & 15)) * STRB + ((lane >> 4) << 4));
    const uint32_t b_off0 = (uint32_t)(((lane & 7) + ((lane >> 4) << 3)) * STRB
                                       + (((lane >> 3) & 1) << 4));

    float acc[2][10][4] = {};

    issue(0, 0);
    issue(1, 1);
    issue(2, 2);

    for (int c = 0; c < NCHUNK; c++) {
        const int stg = c % NSTAGE;
        if (c < NCHUNK - 2)       CP_WAIT(2);
        else if (c == NCHUNK - 2) CP_WAIT(1);
        else                      CP_WAIT(0);
        __syncthreads();

        if (c + 3 < NCHUNK) issue(c + 3, (c + 3) % NSTAGE);

        const uint32_t base = sb + HDR + stg * STG_SZ;
        const uint32_t a_base = base + OFF_A;
        const uint32_t b_base = base + OFF_B + b_off0;

        uint32_t ah[2][4];
#pragma unroll
        for (int mt = 0; mt < 2; mt++) {
            uint32_t ao = a_off0 + (uint32_t)(mt * 16 * STRB);
            ldm_x4(ah[mt], a_base + ao);
        }
#pragma unroll
        for (int jp = 0; jp < 5; jp++) {
            const int j0 = 2 * jp, j1 = 2 * jp + 1;
            uint32_t bh[4];
            ldm_x4(bh, b_base + (uint32_t)(jp * 16 * STRB));
            mma_fp16(acc[0][j0], ah[0], bh[0], bh[1]);
            mma_fp16(acc[1][j0], ah[1], bh[0], bh[1]);
            mma_fp16(acc[0][j1], ah[0], bh[2], bh[3]);
            mma_fp16(acc[1][j1], ah[1], bh[2], bh[3]);
        }
    }

    // --- epilogue: g_part[slot][t][n] = w_t * (acc + bias); plain stores ---
    const float* bp = eb + e * DD;
#pragma unroll
    for (int mt = 0; mt < 2; mt++) {
        int r1 = m0w + mt * 16 + (lane >> 2);
        int r2 = r1 + 8;
        int v1 = tsp[r1], v2 = tsp[r2];
        float w1 = wsp[r1], w2 = wsp[r2];
        float* o1 = (v1 < 0) ? nullptr : &g_part[v1 & 1][(size_t)(v1 >> 1) * DD];
        float* o2 = (v2 < 0) ? nullptr : &g_part[v2 & 1][(size_t)(v2 >> 1) * DD];
#pragma unroll
        for (int jt = 0; jt < 10; jt++) {
            int cc = nb + jt * 8 + 2 * (lane & 3);
            float b0v = bp[cc], b1v = bp[cc + 1];
            if (o1) {
                o1[cc]     = w1 * (acc[mt][jt][0] + b0v);
                o1[cc + 1] = w1 * (acc[mt][jt][1] + b1v);
            }
            if (o2) {
                o2[cc]     = w2 * (acc[mt][jt][2] + b0v);
                o2[cc + 1] = w2 * (acc[mt][jt][3] + b1v);
            }
        }
    }
}

// ---------------------------------------------------------------------------
// Kernel 4: combine — out = part[0] + part[1]
// ---------------------------------------------------------------------------
__global__ __launch_bounds__(256)
void combine_kernel(float4* __restrict__ out4, int n4) {
    int i = blockIdx.x * blockDim.x + threadIdx.x;
    if (i >= n4) return;
    float4 a = ((const float4*)g_part[0])[i];
    float4 b = ((const float4*)g_part[1])[i];
    out4[i] = make_float4(a.x + b.x, a.y + b.y, a.z + b.z, a.w + b.w);
}

// ---------------------------------------------------------------------------
extern "C" void kernel_launch(void* const* d_in, const int* in_sizes, int n_in,
                              void* d_out, int out_size) {
    const float* x  = (const float*)d_in[0];   // [B,S,D]
    const float* gw = (const float*)d_in[1];   // [E,D]
    const float* gb = (const float*)d_in[2];   // [E]
    const float* ew = (const float*)d_in[3];   // [E,D,D]
    const float* eb = (const float*)d_in[4];   // [E,D]
    float* out = (float*)d_out;                // [B,S,D] fp32

    unsigned short *wf;
    cudaGetSymbolAddress((void**)&wf, g_wf);

    int nw8 = EE * DD * DD / 8;                // 57600
    conv_kernel<<<(nw8 + 255) / 256, 256>>>(ew, wf, nw8);   // also zeroes g_cnt

    gate_kernel<<<TT / GTOK, 256>>>(x, gw, gb);             // fused gate+scatter

    cudaFuncSetAttribute(moe_mma_kernel,
                         cudaFuncAttributeMaxDynamicSharedMemorySize, SMEM_TOT);
    dim3 ggrid(TT / BM, 3, EE);                // (256, 3, 8)
    moe_mma_kernel<<<ggrid, 128, SMEM_TOT>>>(eb);

    int n4 = out_size / 4;                     // 1,966,080
    combine_kernel<<<(n4 + 255) / 256, 256>>>((float4*)out, n4);
}

// round 16
// speedup vs baseline: 1.0453x; 1.0453x over previous
#include <cuda_runtime.h>
#include <cuda_fp16.h>
#include <cuda_bf16.h>
#include <cstdint>

// Problem constants (fixed by the dataset)
#define BB   16
#define SS   2048
#define DD   240
#define EE   8
#define TT   (BB * SS)        // 32768 tokens

#define KCH     16            // k per chunk (one mma K)
#define NCHUNK  (DD / KCH)    // 15
#define BM      128           // tokens per CTA tile
#define BN      80            // output cols per CTA (grid.y = 3)
#define STRB    48            // smem row stride in BYTES (conflict-free ldmatrix)
#define NSTAGE  4             // cp.async pipeline stages
#define GTOK    256           // tokens per gate block

// ---------------------------------------------------------------------------
// Device-global scratch (no runtime allocation allowed)
// ---------------------------------------------------------------------------
__device__ int   g_cnt[EE];
__device__ int   g_tok[EE][TT];       // packed: (token << 1) | slot
__device__ float g_gw [EE][TT];
__device__ __align__(16) unsigned short g_xf[(size_t)TT * DD];       // fp16 x
__device__ __align__(16) unsigned short g_wf[(size_t)EE * DD * DD];  // fp16 W
__device__ __align__(16) __half g_part[2][(size_t)TT * DD];          // fp16 partials

// ---------------------------------------------------------------------------
// PTX helpers
// ---------------------------------------------------------------------------
__device__ __forceinline__ void cp16(uint32_t dst, const void* src, int sz) {
    asm volatile("cp.async.ca.shared.global [%0], [%1], 16, %2;"
                 :: "r"(dst), "l"(src), "r"(sz));
}
#define CP_COMMIT() asm volatile("cp.async.commit_group;")
#define CP_WAIT(n)  asm volatile("cp.async.wait_group %0;" :: "n"(n))

__device__ __forceinline__ void ldm_x4(uint32_t (&r)[4], uint32_t addr) {
    asm volatile("ldmatrix.sync.aligned.m8n8.x4.shared.b16 {%0,%1,%2,%3}, [%4];"
                 : "=r"(r[0]), "=r"(r[1]), "=r"(r[2]), "=r"(r[3]) : "r"(addr));
}
__device__ __forceinline__ void mma_fp16(float (&d)[4], const uint32_t (&a)[4],
                                         uint32_t b0, uint32_t b1) {
    asm volatile("mma.sync.aligned.m16n8k16.row.col.f32.f16.f16.f32 "
                 "{%0,%1,%2,%3}, {%4,%5,%6,%7}, {%8,%9}, {%0,%1,%2,%3};"
                 : "+f"(d[0]), "+f"(d[1]), "+f"(d[2]), "+f"(d[3])
                 : "r"(a[0]), "r"(a[1]), "r"(a[2]), "r"(a[3]), "r"(b0), "r"(b1));
}
__device__ __forceinline__ uint32_t smem_u32(const void* p) {
    uint32_t a;
    asm("{ .reg .u64 t; cvta.to.shared.u64 t, %1; cvt.u32.u64 %0, t; }" : "=r"(a) : "l"(p));
    return a;
}

// ---------------------------------------------------------------------------
// Kernel 1: W fp32 -> fp16, 8 elems/thread. Also zeroes expert counters.
// ---------------------------------------------------------------------------
__global__ __launch_bounds__(256)
void conv_kernel(const float* __restrict__ src,
                 unsigned short* __restrict__ df, int n8) {
    if (blockIdx.x == 0 && threadIdx.x < EE) g_cnt[threadIdx.x] = 0;
    int i = blockIdx.x * blockDim.x + threadIdx.x;
    if (i >= n8) return;
    const float4* s4 = (const float4*)(src + (size_t)i * 8);
    float4 v0 = s4[0], v1 = s4[1];
    float v[8] = {v0.x, v0.y, v0.z, v0.w, v1.x, v1.y, v1.z, v1.w};
    unsigned short h[8];
#pragma unroll
    for (int j = 0; j < 8; j++) {
        __half hv = __float2half_rn(v[j]);
        h[j] = *(unsigned short*)&hv;
    }
    *(uint4*)(df + (size_t)i * 8) = *(uint4*)h;
}

// ---------------------------------------------------------------------------
// Kernel 2: fused gating + scatter, float4-vectorized (LDS-issue fix).
// Block = 256 threads = 256 tokens. gate_w staged in smem (float4 broadcast
// reads); x staged in 256x16 chunks with stride-20 rows (16B-aligned float4,
// conflict-free). fp16 conversion of x folded into staging. One thread per
// token: 8 logit accs, scalar top-2 + 2-way softmax, warp-aggregated scatter.
// ---------------------------------------------------------------------------
__global__ __launch_bounds__(256)
void gate_kernel(const float* __restrict__ x,
                 const float* __restrict__ gw,
                 const float* __restrict__ gb) {
    __shared__ __align__(16) float gws[EE * DD];     // 7680 B
    __shared__ __align__(16) float xs[GTOK][20];     // 20480 B, stride 20

    const int tid  = threadIdx.x;
    const int t0   = blockIdx.x * GTOK;
    const int lane = tid & 31;

    for (int i = tid; i < EE * DD; i += 256) gws[i] = gw[i];

    float acc[EE] = {};
    for (int c = 0; c < NCHUNK; c++) {
        __syncthreads();                  // prev chunk consumed (and gws ready)
        // stage 256 tokens x 16 k as float4 (1024 vectors, 4 rounds)
#pragma unroll
        for (int i = 0; i < 4; i++) {
            int idx = tid + 256 * i;      // 0..1023
            int r = idx >> 2, k4 = idx & 3;
            float4 v = *(const float4*)(x + (size_t)(t0 + r) * DD + c * 16 + k4 * 4);
            *(float4*)&xs[r][k4 * 4] = v;
            unsigned short h[4];
            __half h0 = __float2half_rn(v.x); h[0] = *(unsigned short*)&h0;
            __half h1 = __float2half_rn(v.y); h[1] = *(unsigned short*)&h1;
            __half h2 = __float2half_rn(v.z); h[2] = *(unsigned short*)&h2;
            __half h3 = __float2half_rn(v.w); h[3] = *(unsigned short*)&h3;
            *(uint2*)(g_xf + (size_t)(t0 + r) * DD + c * 16 + k4 * 4) = *(uint2*)h;
        }
        __syncthreads();
#pragma unroll
        for (int k4 = 0; k4 < 4; k4++) {
            float4 xv = *(const float4*)&xs[tid][k4 * 4];
#pragma unroll
            for (int e = 0; e < EE; e++) {
                float4 gv = *(const float4*)&gws[e * DD + c * 16 + k4 * 4];
                acc[e] += xv.x * gv.x + xv.y * gv.y + xv.z * gv.z + xv.w * gv.w;
            }
        }
    }

#pragma unroll
    for (int e = 0; e < EE; e++) acc[e] += gb[e];

    // top-2 (earliest index on ties, matching jax top_k)
    int b1 = 0;
#pragma unroll
    for (int e = 1; e < EE; e++) if (acc[e] > acc[b1]) b1 = e;
    int b2 = (b1 == 0) ? 1 : 0;
#pragma unroll
    for (int e = 0; e < EE; e++) {
        if (e == b1 || e == b2) continue;
        if (acc[e] > acc[b2]) b2 = e;
    }
    float m  = fmaxf(acc[b1], acc[b2]);
    float e1 = __expf(acc[b1] - m);
    float e2 = __expf(acc[b2] - m);
    float inv = 1.f / (e1 + e2);
    float w1 = e1 * inv, w2 = e2 * inv;

    // fused scatter: warp-aggregated atomics, packed (token<<1)|slot
    const int t = t0 + tid;
#pragma unroll
    for (int slot = 0; slot < 2; slot++) {
        int   e = slot ? b2 : b1;
        float w = slot ? w2 : w1;
        unsigned mask = __match_any_sync(0xffffffffu, e);
        int leader = __ffs(mask) - 1;
        int rank   = __popc(mask & ((1u << lane) - 1));
        int base = 0;
        if (lane == leader) base = atomicAdd(&g_cnt[e], __popc(mask));
        base = __shfl_sync(mask, base, leader);
        int pos = base + rank;
        g_tok[e][pos] = (t << 1) | slot;
        g_gw [e][pos] = w;
    }
}

// ---------------------------------------------------------------------------
// Kernel 3: grouped expert GEMM on warp tensor cores, fp16 single-term.
// grid = (TT/BM, 3, E). 128 threads = 4 m-warps x 1 n-warp (warp tile 32x80).
// B fragments loaded as jt-pairs via ldm_x4. 4-stage cp.async pipeline,
// one __syncthreads per chunk. Epilogue: half2 stores into fp16 g_part.
// ---------------------------------------------------------------------------
#define HDR     1024
#define A_SZ    (BM * STRB)            // 6144 B per A stage
#define B_SZ    (BN * STRB)            // 3840 B per B stage
#define STG_SZ  (A_SZ + B_SZ)          // 9984 B per stage
#define OFF_A   0
#define OFF_B   A_SZ
#define SMEM_TOT (HDR + NSTAGE * STG_SZ)   // 40960 B -> 4 CTAs/SM

__global__ __launch_bounds__(128, 4)
void moe_mma_kernel(const float* __restrict__ eb) {
    const int e   = blockIdx.z;
    const int cnt = g_cnt[e];
    const int m0  = blockIdx.x * BM;
    if (m0 >= cnt) return;
    const int nb  = blockIdx.y * BN;      // 0, 80, 160

    extern __shared__ __align__(16) char smem[];
    int*   tsp = (int*)  smem;
    float* wsp = (float*)(smem + 512);
    const uint32_t sb = smem_u32(smem);

    const int tid  = threadIdx.x;
    const int lane = tid & 31;
    const int wid  = tid >> 5;           // m-warp 0..3
    const int m0w  = wid * 32;

    if (tid < BM) {
        int gr = m0 + tid;
        if (gr < cnt) { tsp[tid] = g_tok[e][gr]; wsp[tid] = g_gw[e][gr]; }
        else          { tsp[tid] = -1;           wsp[tid] = 0.f; }
    }
    __syncthreads();

    // --- cp.async issue for chunk c into stage stg ---
    auto issue = [&](int c, int stg) {
        uint32_t base = sb + HDR + stg * STG_SZ;
#pragma unroll
        for (int s = tid; s < BM * 2; s += 128) {
            int row = s >> 1, h = s & 1;
            int v = tsp[row];
            size_t so = (size_t)((v < 0) ? 0 : (v >> 1)) * DD + c * KCH + h * 8;
            int  sz = (v >= 0) ? 16 : 0;
            uint32_t d = (uint32_t)(row * STRB + h * 16);
            cp16(base + OFF_A + d, g_xf + so, sz);
        }
#pragma unroll
        for (int s = tid; s < BN * 2; s += 128) {
            int row = s >> 1, h = s & 1;
            size_t so = ((size_t)e * DD + nb + row) * DD + c * KCH + h * 8;
            uint32_t d = (uint32_t)(row * STRB + h * 16);
            cp16(base + OFF_B + d, g_wf + so, 16);
        }
        CP_COMMIT();
    };

    const uint32_t a_off0 = (uint32_t)((m0w + (lane & 15)) * STRB + ((lane >> 4) << 4));
    const uint32_t b_off0 = (uint32_t)(((lane & 7) + ((lane >> 4) << 3)) * STRB
                                       + (((lane >> 3) & 1) << 4));

    float acc[2][10][4] = {};

    issue(0, 0);
    issue(1, 1);
    issue(2, 2);

    for (int c = 0; c < NCHUNK; c++) {
        const int stg = c % NSTAGE;
        if (c < NCHUNK - 2)       CP_WAIT(2);
        else if (c == NCHUNK - 2) CP_WAIT(1);
        else                      CP_WAIT(0);
        __syncthreads();

        if (c + 3 < NCHUNK) issue(c + 3, (c + 3) % NSTAGE);

        const uint32_t base = sb + HDR + stg * STG_SZ;
        const uint32_t a_base = base + OFF_A;
        const uint32_t b_base = base + OFF_B + b_off0;

        uint32_t ah[2][4];
#pragma unroll
        for (int mt = 0; mt < 2; mt++) {
            uint32_t ao = a_off0 + (uint32_t)(mt * 16 * STRB);
            ldm_x4(ah[mt], a_base + ao);
        }
#pragma unroll
        for (int jp = 0; jp < 5; jp++) {
            const int j0 = 2 * jp, j1 = 2 * jp + 1;
            uint32_t bh[4];
            ldm_x4(bh, b_base + (uint32_t)(jp * 16 * STRB));
            mma_fp16(acc[0][j0], ah[0], bh[0], bh[1]);
            mma_fp16(acc[1][j0], ah[1], bh[0], bh[1]);
            mma_fp16(acc[0][j1], ah[0], bh[2], bh[3]);
            mma_fp16(acc[1][j1], ah[1], bh[2], bh[3]);
        }
    }

    // --- epilogue: g_part[slot][t][n] = w_t * (acc + bias); half2 stores ---
    const float* bp = eb + e * DD;
#pragma unroll
    for (int mt = 0; mt < 2; mt++) {
        int r1 = m0w + mt * 16 + (lane >> 2);
        int r2 = r1 + 8;
        int v1 = tsp[r1], v2 = tsp[r2];
        float w1 = wsp[r1], w2 = wsp[r2];
        __half* o1 = (v1 < 0) ? nullptr : &g_part[v1 & 1][(size_t)(v1 >> 1) * DD];
        __half* o2 = (v2 < 0) ? nullptr : &g_part[v2 & 1][(size_t)(v2 >> 1) * DD];
#pragma unroll
        for (int jt = 0; jt < 10; jt++) {
            int cc = nb + jt * 8 + 2 * (lane & 3);   // always even
            float b0v = bp[cc], b1v = bp[cc + 1];
            if (o1) {
                *(__half2*)&o1[cc] = __floats2half2_rn(
                    w1 * (acc[mt][jt][0] + b0v), w1 * (acc[mt][jt][1] + b1v));
            }
            if (o2) {
                *(__half2*)&o2[cc] = __floats2half2_rn(
                    w2 * (acc[mt][jt][2] + b0v), w2 * (acc[mt][jt][3] + b1v));
            }
        }
    }
}

// ---------------------------------------------------------------------------
// Kernel 4: combine — out = part[0] + part[1]  (fp16 partials -> fp32 out).
// 8 elements per thread.
// ---------------------------------------------------------------------------
__global__ __launch_bounds__(256)
void combine_kernel(float4* __restrict__ out4, int n8) {
    int i = blockIdx.x * blockDim.x + threadIdx.x;
    if (i >= n8) return;
    uint4 a = ((const uint4*)g_part[0])[i];
    uint4 b = ((const uint4*)g_part[1])[i];
    const __half2* ah = (const __half2*)&a;
    const __half2* bh = (const __half2*)&b;
    float4 o0, o1;
    float2 s0 = __half22float2(ah[0]), t0 = __half22float2(bh[0]);
    float2 s1 = __half22float2(ah[1]), t1 = __half22float2(bh[1]);
    float2 s2 = __half22float2(ah[2]), t2 = __half22float2(bh[2]);
    float2 s3 = __half22float2(ah[3]), t3 = __half22float2(bh[3]);
    o0 = make_float4(s0.x + t0.x, s0.y + t0.y, s1.x + t1.x, s1.y + t1.y);
    o1 = make_float4(s2.x + t2.x, s2.y + t2.y, s3.x + t3.x, s3.y + t3.y);
    out4[2 * i]     = o0;
    out4[2 * i + 1] = o1;
}

// ---------------------------------------------------------------------------
extern "C" void kernel_launch(void* const* d_in, const int* in_sizes, int n_in,
                              void* d_out, int out_size) {
    const float* x  = (const float*)d_in[0];   // [B,S,D]
    const float* gw = (const float*)d_in[1];   // [E,D]
    const float* gb = (const float*)d_in[2];   // [E]
    const float* ew = (const float*)d_in[3];   // [E,D,D]
    const float* eb = (const float*)d_in[4];   // [E,D]
    float* out = (float*)d_out;                // [B,S,D] fp32

    unsigned short *wf;
    cudaGetSymbolAddress((void**)&wf, g_wf);

    int nw8 = EE * DD * DD / 8;                // 57600
    conv_kernel<<<(nw8 + 255) / 256, 256>>>(ew, wf, nw8);   // also zeroes g_cnt

    gate_kernel<<<TT / GTOK, 256>>>(x, gw, gb);             // fused gate+scatter

    cudaFuncSetAttribute(moe_mma_kernel,
                         cudaFuncAttributeMaxDynamicSharedMemorySize, SMEM_TOT);
    dim3 ggrid(TT / BM, 3, EE);                // (256, 3, 8)
    moe_mma_kernel<<<ggrid, 128, SMEM_TOT>>>(eb);

    int n8 = out_size / 8;                     // 983040
    combine_kernel<<<(n8 + 255) / 256, 256>>>((float4*)out, n8);
}